// round 11
// baseline (speedup 1.0000x reference)
#include <cuda_runtime.h>
#include <cstdint>
#include <cstddef>

#define NF   131072
#define INS  256
#define HID  1024
#define OUTS 256
#define NE   16
#define TM   128
#define HC   32
#define NCHUNK (HID / HC)
#define GRID2 (NF / TM + NE)

typedef unsigned int u32;

// ---------------- routing scratch ----------------
__device__ int g_cnt[NE];
__device__ int g_off[NE + 1];
__device__ int g_cur[NE];
__device__ int g_tile[NE + 1];
__device__ int g_perm[NF];
__device__ int g_ids_is64;
__device__ int g_done;

__device__ __forceinline__ int get_id(const void* ids, int i, int is64) {
    int e = is64 ? (int)((const long long*)ids)[i] : ((const int*)ids)[i];
    return e & 15;
}

__global__ void k_init(const long long* __restrict__ ids) {
    __shared__ int bad;
    if (threadIdx.x == 0) bad = 0;
    __syncthreads();
    for (int i = threadIdx.x; i < 4096; i += 256) {
        unsigned long long v = (unsigned long long)ids[i];
        if (v > 15ULL) bad = 1;
    }
    __syncthreads();
    if (threadIdx.x == 0) { g_ids_is64 = bad ? 0 : 1; g_done = 0; }
    if (threadIdx.x < NE) g_cnt[threadIdx.x] = 0;
}

__global__ void k_count_scan(const void* __restrict__ ids) {
    __shared__ int h[NE];
    __shared__ int lastf;
    int tid = threadIdx.x;
    if (tid < NE) h[tid] = 0;
    __syncthreads();
    int is64 = g_ids_is64;
    int base = blockIdx.x * 512;
    atomicAdd(&h[get_id(ids, base + tid, is64)], 1);
    atomicAdd(&h[get_id(ids, base + 256 + tid, is64)], 1);
    __syncthreads();
    if (tid < NE) atomicAdd(&g_cnt[tid], h[tid]);
    __threadfence();
    if (tid == 0) lastf = (atomicAdd(&g_done, 1) == 255);
    __syncthreads();
    if (lastf && tid == 0) {
        int o = 0, t = 0;
        for (int e = 0; e < NE; e++) {
            g_off[e] = o; g_cur[e] = o; g_tile[e] = t;
            o += g_cnt[e];
            t += (g_cnt[e] + TM - 1) / TM;
        }
        g_off[NE] = o; g_tile[NE] = t;
    }
}

__global__ void k_scatter(const void* __restrict__ ids) {
    __shared__ int h[NE], bm[NE];
    int tid = threadIdx.x;
    if (tid < NE) h[tid] = 0;
    __syncthreads();
    int is64 = g_ids_is64;
    int base = blockIdx.x * 512;
    int e0 = get_id(ids, base + tid, is64);
    int e1 = get_id(ids, base + 256 + tid, is64);
    atomicAdd(&h[e0], 1);
    atomicAdd(&h[e1], 1);
    __syncthreads();
    if (tid < NE) { bm[tid] = atomicAdd(&g_cur[tid], h[tid]); h[tid] = 0; }
    __syncthreads();
    int r0 = atomicAdd(&h[e0], 1); g_perm[bm[e0] + r0] = base + tid;
    int r1 = atomicAdd(&h[e1], 1); g_perm[bm[e1] + r1] = base + 256 + tid;
}

// ---------------- helpers ----------------
__device__ __forceinline__ u32 f2tf32(float f) {
    u32 u; asm("cvt.rna.tf32.f32 %0, %1;" : "=r"(u) : "f"(f)); return u;
}
__device__ __forceinline__ u32 smem_u32(const void* p) {
    u32 a;
    asm("{ .reg .u64 t; cvta.to.shared.u64 t, %1; cvt.u32.u64 %0, t; }" : "=r"(a) : "l"(p));
    return a;
}
__device__ __forceinline__ void cpa16(u32 dst, const void* src) {
    asm volatile("cp.async.cg.shared.global [%0], [%1], 16;" :: "r"(dst), "l"(src));
}
#define CPA_COMMIT() asm volatile("cp.async.commit_group;" ::: "memory")
#define CPA_WAIT0()  asm volatile("cp.async.wait_group 0;" ::: "memory")
#define BAR_SYNC(id, n) asm volatile("bar.sync %0, %1;" :: "n"(id), "n"(n) : "memory")

__device__ __forceinline__ void mma8(float* d, const u32* a, const u32* b) {
    asm volatile("mma.sync.aligned.m16n8k8.row.col.f32.tf32.tf32.f32 "
        "{%0,%1,%2,%3}, {%4,%5,%6,%7}, {%8,%9}, {%0,%1,%2,%3};"
        : "+f"(d[0]), "+f"(d[1]), "+f"(d[2]), "+f"(d[3])
        : "r"(a[0]), "r"(a[1]), "r"(a[2]), "r"(a[3]), "r"(b[0]), "r"(b[1]));
}

// ---------------- SMEM layout (u32 offsets) ----------------
// sXp  [128 r][128 u64]  X as (k,k+4) tf32 pairs, u64-XOR swizzled   131072 B
//      pair idx64(r,p) = r*128 + (p ^ ((r&3)<<2))
// sW1r [256][32]  raw fp32 W1 chunk, k-XOR swizzled                   32768 B
// sW2r [32][256]  raw fp32 W2 chunk, k-XOR swizzled                   32768 B
// sH   [128][36]  tf32 h tile (banks 4*gid+tig: conflict-free)        18432 B
// sb2[256], toks[128]
#define OFF_X    0
#define OFF_W1   32768
#define OFF_W2   40960
#define OFF_H    49152
#define OFF_B2   53760
#define OFF_TOKS 54016
#define SMEM_U32 54144
#define SMEM_BYTES (SMEM_U32 * 4)   // 216576
#define HSd  36

__global__ void __launch_bounds__(384, 1)
k_mlp(const float* __restrict__ X,  const float* __restrict__ W1,
      const float* __restrict__ B1v, const float* __restrict__ W2,
      const float* __restrict__ B2v, float* __restrict__ Y)
{
    extern __shared__ u32 smu[];
    u32*   sXp  = smu + OFF_X;
    u32*   sW1r = smu + OFF_W1;
    u32*   sW2r = smu + OFF_W2;
    u32*   sH   = smu + OFF_H;
    float* sb2  = (float*)(smu + OFF_B2);
    int*   toks = (int*)(smu + OFF_TOKS);
    u32 sbase = smem_u32(smu);

    int tid  = threadIdx.x;
    int lane = tid & 31;
    int gid  = lane >> 2;
    int tig  = lane & 3;
    u32 swz  = (u32)(tig << 3);

    int bid = blockIdx.x;
    if (bid >= g_tile[NE]) return;
    int e = 0;
    while (bid >= g_tile[e + 1]) e++;
    int goff = g_off[e];
    int cnt  = g_off[e + 1] - goff;
    int t0   = (bid - g_tile[e]) * TM;
    int vcnt = min(TM, cnt - t0);

    const float* w1e = W1  + (size_t)e * INS * HID;
    const float* w2e = W2  + (size_t)e * HID * OUTS;
    const float* b1e = B1v + (size_t)e * HID;

    // ---- Init: toks + b2 ----
    if (tid < TM) {
        int slot = t0 + tid;
        if (slot >= cnt) slot = cnt - 1;
        toks[tid] = g_perm[goff + slot];
    }
    if (tid < 256) sb2[tid] = B2v[(size_t)e * OUTS + tid];
    __syncthreads();   // toks ready

    // ---- Prologue: weight chunk 0 (per-group cp.async streams) ----
    if (tid >= 256) {   // producers own W1 stream
        int ptid = tid - 256;
        #pragma unroll
        for (int i = 0; i < 16; i++) {
            int idx = i * 128 + ptid;
            int k = idx >> 3, c = idx & 7;
            int c2 = c ^ ((k & 3) << 1);
            cpa16(sbase + (OFF_W1 + k * 32 + c2 * 4) * 4, w1e + (size_t)k * HID + c * 4);
        }
        CPA_COMMIT();
    } else {            // consumers own W2 stream
        #pragma unroll
        for (int i = 0; i < 8; i++) {
            int idx = i * 256 + tid;
            int k = idx >> 6, c = idx & 63;
            int c2 = c ^ ((k & 3) << 1);
            cpa16(sbase + (OFF_W2 + k * 256 + c2 * 4) * 4, w2e + (size_t)k * OUTS + c * 4);
        }
        CPA_COMMIT();
    }

    // ---- X cooperative load into swizzled (k,k+4) pair layout ----
    for (int g = tid; g < 4096; g += 384) {
        int r = g >> 5;
        int c = g & 31;
        const float* xr = X + (size_t)toks[r] * INS + c * 8;
        float4 va = *(const float4*)xr;
        float4 vb = *(const float4*)(xr + 4);
        uint4 p01 = { f2tf32(va.x), f2tf32(vb.x), f2tf32(va.y), f2tf32(vb.y) };
        uint4 p23 = { f2tf32(va.z), f2tf32(vb.z), f2tf32(va.w), f2tf32(vb.w) };
        u32 pb = (u32)((c * 4) ^ ((r & 3) << 2));
        *(uint4*)&sXp[(r * 128 + pb) * 2]     = p01;
        *(uint4*)&sXp[(r * 128 + pb) * 2 + 4] = p23;
    }
    __syncthreads();   // X visible to all

    if (tid >= 256) {
        // =================== PRODUCER (warps 8-11): GEMM1 ===================
        int ptid = tid - 256;
        int pwid = ptid >> 5;          // 0..3
        int m0p  = pwid * 32;
        u32 swp  = (u32)((gid & 3) << 2);
        const int rb0 = (m0p + gid) * 128;
        const int rb1 = (m0p + 8 + gid) * 128;
        const int rb2 = (m0p + 16 + gid) * 128;
        const int rb3 = (m0p + 24 + gid) * 128;
        u32 ciP[4];
        #pragma unroll
        for (int nb = 0; nb < 4; nb++) ciP[nb] = (u32)(8 * nb + gid) ^ swz;

#define G1_LOADA(buf, kt) do {                                          \
    u32 pp = (u32)((kt) * 4 + tig) ^ swp;                               \
    uint2 A00 = *(const uint2*)&sXp[(rb0 + pp) * 2];                    \
    uint2 A01 = *(const uint2*)&sXp[(rb1 + pp) * 2];                    \
    uint2 A10 = *(const uint2*)&sXp[(rb2 + pp) * 2];                    \
    uint2 A11 = *(const uint2*)&sXp[(rb3 + pp) * 2];                    \
    aX[buf][0][0]=A00.x; aX[buf][0][2]=A00.y;                           \
    aX[buf][0][1]=A01.x; aX[buf][0][3]=A01.y;                           \
    aX[buf][1][0]=A10.x; aX[buf][1][2]=A10.y;                           \
    aX[buf][1][1]=A11.x; aX[buf][1][3]=A11.y;                           \
} while (0)

#define G1_LOADB(buf, kt) do {                                          \
    int kk = (kt) * 8;                                                  \
    bW[buf][0] = sW1r[(kk + tig) * 32 + ciP[0]];                        \
    bW[buf][1] = sW1r[(kk + tig + 4) * 32 + ciP[0]];                    \
    bW[buf][2] = sW1r[(kk + tig) * 32 + ciP[1]];                        \
    bW[buf][3] = sW1r[(kk + tig + 4) * 32 + ciP[1]];                    \
    bW[buf][4] = sW1r[(kk + tig) * 32 + ciP[2]];                        \
    bW[buf][5] = sW1r[(kk + tig + 4) * 32 + ciP[2]];                    \
    bW[buf][6] = sW1r[(kk + tig) * 32 + ciP[3]];                        \
    bW[buf][7] = sW1r[(kk + tig + 4) * 32 + ciP[3]];                    \
} while (0)

#define G1_COMP(buf) do {                                               \
    _Pragma("unroll")                                                   \
    for (int nb = 0; nb < 4; nb++) {                                    \
        u32 b[2] = { f2tf32(__uint_as_float(bW[buf][2*nb])),            \
                     f2tf32(__uint_as_float(bW[buf][2*nb+1])) };        \
        mma8(acc1[0][nb], aX[buf][0], b);                               \
        mma8(acc1[1][nb], aX[buf][1], b);                               \
    }                                                                   \
} while (0)

        for (int n = 0; n < NCHUNK; n++) {
            int h0 = n * HC;
            CPA_WAIT0();               // W1(n) landed (own stream)

            // b1 prefetch for epilogue (overlaps GEMM1)
            float2 bv[4];
            #pragma unroll
            for (int nb = 0; nb < 4; nb++)
                bv[nb] = *(const float2*)(b1e + h0 + 8 * nb + 2 * tig);

            float acc1[2][4][4];
            #pragma unroll
            for (int mt = 0; mt < 2; mt++)
                #pragma unroll
                for (int nb = 0; nb < 4; nb++)
                    #pragma unroll
                    for (int j = 0; j < 4; j++) acc1[mt][nb][j] = 0.0f;

            {
                u32 aX[2][2][4];
                u32 bW[2][8];
                G1_LOADA(0, 0); G1_LOADB(0, 0);
                #pragma unroll 8
                for (int kt = 0; kt < 32; kt++) {
                    int cur = kt & 1, nxt = cur ^ 1;
                    int ktn = (kt + 1) & 31;
                    G1_LOADA(nxt, ktn);
                    G1_LOADB(nxt, ktn);
                    G1_COMP(cur);
                }
            }

            BAR_SYNC(3, 128);          // all P done reading W1(n)
            if (n + 1 < NCHUNK) {      // issue W1(n+1)
                int h1 = h0 + HC;
                #pragma unroll
                for (int i = 0; i < 16; i++) {
                    int idx = i * 128 + ptid;
                    int k = idx >> 3, c = idx & 7;
                    int c2 = c ^ ((k & 3) << 1);
                    cpa16(sbase + (OFF_W1 + k * 32 + c2 * 4) * 4,
                          w1e + (size_t)k * HID + h1 + c * 4);
                }
                CPA_COMMIT();
            }

            BAR_SYNC(2, 384);          // EMPTY: consumers done with sH(n-1)

            // epilogue: relu(acc + b1) -> tf32 -> sH
            #pragma unroll
            for (int mt = 0; mt < 2; mt++) {
                int r = m0p + 16 * mt + gid;
                #pragma unroll
                for (int nb = 0; nb < 4; nb++) {
                    int c = 8 * nb + 2 * tig;
                    uint2 lo = { f2tf32(fmaxf(acc1[mt][nb][0] + bv[nb].x, 0.0f)),
                                 f2tf32(fmaxf(acc1[mt][nb][1] + bv[nb].y, 0.0f)) };
                    uint2 hi = { f2tf32(fmaxf(acc1[mt][nb][2] + bv[nb].x, 0.0f)),
                                 f2tf32(fmaxf(acc1[mt][nb][3] + bv[nb].y, 0.0f)) };
                    *(uint2*)&sH[r * HSd + c]       = lo;
                    *(uint2*)&sH[(r + 8) * HSd + c] = hi;
                }
            }
            BAR_SYNC(1, 384);          // FULL(n): sH ready
        }
        return;   // producers done (consumers finish Y)
    }

    // =================== CONSUMER (warps 0-7): GEMM2 ===================
    {
        int cwid = tid >> 5;           // 0..7
        int m02 = (cwid & 1) * 64;
        int n02 = (cwid >> 1) * 64;
        u32 cia[8];
        #pragma unroll
        for (int nb = 0; nb < 8; nb++) cia[nb] = (u32)(n02 + 8 * nb + gid) ^ swz;

        float yacc[4][8][4];
        #pragma unroll
        for (int mt = 0; mt < 4; mt++)
            #pragma unroll
            for (int nb = 0; nb < 8; nb++)
                #pragma unroll
                for (int j = 0; j < 4; j++) yacc[mt][nb][j] = 0.0f;

        BAR_SYNC(2, 384);              // pre-charge EMPTY(0)

        for (int n = 0; n < NCHUNK; n++) {
            BAR_SYNC(1, 384);          // FULL(n): sH(n) ready
            CPA_WAIT0();               // W2(n) landed (own stream)

            #pragma unroll
            for (int kt = 0; kt < 4; kt++) {
                int k0 = kt * 8;
                u32 ah[4][4];
                #pragma unroll
                for (int mt = 0; mt < 4; mt++) {
                    int r = m02 + 16 * mt + gid;
                    ah[mt][0] = sH[r * HSd + k0 + tig];
                    ah[mt][1] = sH[(r + 8) * HSd + k0 + tig];
                    ah[mt][2] = sH[r * HSd + k0 + tig + 4];
                    ah[mt][3] = sH[(r + 8) * HSd + k0 + tig + 4];
                }
                #pragma unroll
                for (int nb = 0; nb < 8; nb++) {
                    u32 r0w = sW2r[(k0 + tig) * 256 + cia[nb]];
                    u32 r1w = sW2r[(k0 + tig + 4) * 256 + cia[nb]];
                    u32 b[2] = { f2tf32(__uint_as_float(r0w)), f2tf32(__uint_as_float(r1w)) };
                    mma8(yacc[0][nb], ah[0], b);
                    mma8(yacc[1][nb], ah[1], b);
                    mma8(yacc[2][nb], ah[2], b);
                    mma8(yacc[3][nb], ah[3], b);
                }
            }

            if (n + 1 < NCHUNK) {
                BAR_SYNC(4, 256);      // all C done reading W2(n) & sH(n)
                int h1 = (n + 1) * HC;
                #pragma unroll
                for (int i = 0; i < 8; i++) {
                    int idx = i * 256 + tid;
                    int k = idx >> 6, c = idx & 63;
                    int c2 = c ^ ((k & 3) << 1);
                    cpa16(sbase + (OFF_W2 + k * 256 + c2 * 4) * 4,
                          w2e + (size_t)(h1 + k) * OUTS + c * 4);
                }
                CPA_COMMIT();
                BAR_SYNC(2, 384);      // EMPTY: sH free for producers
            }
        }

        // ---- Final: Y + b2, masked scatter store ----
        #pragma unroll
        for (int mt = 0; mt < 4; mt++) {
            int  rA = m02 + 16 * mt + gid, rB = rA + 8;
            bool vA = rA < vcnt, vB = rB < vcnt;
            float* yA = Y + (size_t)toks[rA] * OUTS;
            float* yB = Y + (size_t)toks[rB] * OUTS;
            #pragma unroll
            for (int nb = 0; nb < 8; nb++) {
                int c = n02 + 8 * nb + 2 * tig;
                float ba = sb2[c], bb = sb2[c + 1];
                if (vA) { float2 v = { yacc[mt][nb][0] + ba, yacc[mt][nb][1] + bb }; *(float2*)(yA + c) = v; }
                if (vB) { float2 v = { yacc[mt][nb][2] + ba, yacc[mt][nb][3] + bb }; *(float2*)(yB + c) = v; }
            }
        }
    }
}

// ---------------- launch ----------------
extern "C" void kernel_launch(void* const* d_in, const int* in_sizes, int n_in,
                              void* d_out, int out_size)
{
    (void)out_size;
    const float *X = 0, *W1 = 0, *B1 = 0, *W2 = 0, *B2 = 0;
    const void  *IDS = 0;
    for (int i = 0; i < n_in; i++) {
        switch (in_sizes[i]) {
            case 33554432: X = (const float*)d_in[i]; break;
            case 4194304:  if (!W1) W1 = (const float*)d_in[i];
                           else     W2 = (const float*)d_in[i];
                           break;
            case 16384:    B1 = (const float*)d_in[i]; break;
            case 4096:     B2 = (const float*)d_in[i]; break;
            case 131072:   IDS = d_in[i]; break;
            default: break;
        }
    }
    float* Y = (float*)d_out;

    cudaFuncSetAttribute(k_mlp, cudaFuncAttributeMaxDynamicSharedMemorySize, SMEM_BYTES);

    k_init<<<1, 256>>>((const long long*)IDS);
    k_count_scan<<<256, 256>>>(IDS);
    k_scatter<<<256, 256>>>(IDS);
    k_mlp<<<GRID2, 384, SMEM_BYTES>>>(X, W1, B1, W2, B2, Y);
}

// round 12
// speedup vs baseline: 1.9566x; 1.9566x over previous
#include <cuda_runtime.h>
#include <cstdint>
#include <cstddef>

#define NF   131072
#define INS  256
#define HID  1024
#define OUTS 256
#define NE   16
#define TM   128
#define HC   32
#define NCHUNK (HID / HC)
#define GRID2 (NF / TM + NE)

typedef unsigned int u32;

// ---------------- routing + weight-image scratch ----------------
__device__ int g_cnt[NE];
__device__ int g_off[NE + 1];
__device__ int g_cur[NE];
__device__ int g_tile[NE + 1];
__device__ int g_perm[NF];
__device__ int g_ids_is64;
__device__ int g_done;
// Pre-converted tf32 weight images, pair-packed + bank-XOR'd, one 8192-u32
// (32 KB) smem-image per (expert, chunk).
__device__ u32 gW1c[NE * NCHUNK * 8192];
__device__ u32 gW2c[NE * NCHUNK * 8192];

__device__ __forceinline__ int get_id(const void* ids, int i, int is64) {
    int e = is64 ? (int)((const long long*)ids)[i] : ((const int*)ids)[i];
    return e & 15;
}

__device__ __forceinline__ u32 f2tf32(float f) {
    u32 u; asm("cvt.rna.tf32.f32 %0, %1;" : "=r"(u) : "f"(f)); return u;
}

// ---------------- launch 1: weight convert/relayout + init ----------------
// grid 512 = (e, n) chunk pairs; block 0 also probes ids dtype + zeroes counters.
__global__ void k_pre(const float* __restrict__ W1, const float* __restrict__ W2,
                      const long long* __restrict__ ids)
{
    int tid = threadIdx.x;
    int e = blockIdx.x >> 5;
    int n = blockIdx.x & 31;

    if (blockIdx.x == 0) {
        __shared__ int bad;
        if (tid == 0) bad = 0;
        __syncthreads();
        for (int i = tid; i < 4096; i += 256) {
            unsigned long long v = (unsigned long long)ids[i];
            if (v > 15ULL) bad = 1;
        }
        __syncthreads();
        if (tid == 0) { g_ids_is64 = bad ? 0 : 1; g_done = 0; }
        if (tid < NE) g_cnt[tid] = 0;
    }

    // W1 chunk image: src rows k=0..255, cols j=0..31 (h = n*32+j)
    // pair = (k>>3)*4 + (k&3), hi = (k>>2)&1, col' = j ^ ((k&3)<<2)
    // u32 idx = pair*64 + col'*2 + hi
    {
        int k = tid;
        const float* src = W1 + (size_t)e * INS * HID + (size_t)k * HID + n * 32;
        u32* dst = gW1c + (size_t)blockIdx.x * 8192
                 + ((k >> 3) * 4 + (k & 3)) * 64 + ((k >> 2) & 1);
        u32 sx = (u32)((k & 3) << 2);
        #pragma unroll
        for (int j4 = 0; j4 < 8; j4++) {
            float4 v = *(const float4*)(src + j4 * 4);
            dst[((j4 * 4 + 0) ^ sx) * 2] = f2tf32(v.x);
            dst[((j4 * 4 + 1) ^ sx) * 2] = f2tf32(v.y);
            dst[((j4 * 4 + 2) ^ sx) * 2] = f2tf32(v.z);
            dst[((j4 * 4 + 3) ^ sx) * 2] = f2tf32(v.w);
        }
    }

    // W2 chunk image: src rows k=0..31 (h = n*32+k), cols c=0..255
    // pair = (k>>3)*4 + (k&3), hi = (k>>2)&1, col' = c ^ ((k&3)<<2)
    // u32 idx = pair*512 + col'*2 + hi
    {
        int k  = tid >> 3;
        int cg = tid & 7;
        const float* src = W2 + (size_t)e * HID * OUTS + (size_t)(n * 32 + k) * OUTS + cg * 32;
        u32* dst = gW2c + (size_t)blockIdx.x * 8192
                 + ((k >> 3) * 4 + (k & 3)) * 512 + ((k >> 2) & 1);
        u32 sx = (u32)((k & 3) << 2);
        #pragma unroll
        for (int c4 = 0; c4 < 8; c4++) {
            float4 v = *(const float4*)(src + c4 * 4);
            int c = cg * 32 + c4 * 4;
            dst[((c + 0) ^ sx) * 2] = f2tf32(v.x);
            dst[((c + 1) ^ sx) * 2] = f2tf32(v.y);
            dst[((c + 2) ^ sx) * 2] = f2tf32(v.z);
            dst[((c + 3) ^ sx) * 2] = f2tf32(v.w);
        }
    }
}

// ---------------- launch 2: histogram, last block scans ----------------
__global__ void k_count_scan(const void* __restrict__ ids) {
    __shared__ int h[NE];
    __shared__ int lastf;
    int tid = threadIdx.x;
    if (tid < NE) h[tid] = 0;
    __syncthreads();
    int is64 = g_ids_is64;
    int base = blockIdx.x * 512;
    atomicAdd(&h[get_id(ids, base + tid, is64)], 1);
    atomicAdd(&h[get_id(ids, base + 256 + tid, is64)], 1);
    __syncthreads();
    if (tid < NE) atomicAdd(&g_cnt[tid], h[tid]);
    __threadfence();
    if (tid == 0) lastf = (atomicAdd(&g_done, 1) == 255);
    __syncthreads();
    if (lastf && tid == 0) {
        int o = 0, t = 0;
        for (int e = 0; e < NE; e++) {
            g_off[e] = o; g_cur[e] = o; g_tile[e] = t;
            o += g_cnt[e];
            t += (g_cnt[e] + TM - 1) / TM;
        }
        g_off[NE] = o; g_tile[NE] = t;
    }
}

// ---------------- launch 3: scatter ----------------
__global__ void k_scatter(const void* __restrict__ ids) {
    __shared__ int h[NE], bm[NE];
    int tid = threadIdx.x;
    if (tid < NE) h[tid] = 0;
    __syncthreads();
    int is64 = g_ids_is64;
    int base = blockIdx.x * 512;
    int e0 = get_id(ids, base + tid, is64);
    int e1 = get_id(ids, base + 256 + tid, is64);
    atomicAdd(&h[e0], 1);
    atomicAdd(&h[e1], 1);
    __syncthreads();
    if (tid < NE) { bm[tid] = atomicAdd(&g_cur[tid], h[tid]); h[tid] = 0; }
    __syncthreads();
    int r0 = atomicAdd(&h[e0], 1); g_perm[bm[e0] + r0] = base + tid;
    int r1 = atomicAdd(&h[e1], 1); g_perm[bm[e1] + r1] = base + 256 + tid;
}

// ---------------- helpers ----------------
__device__ __forceinline__ u32 smem_u32(const void* p) {
    u32 a;
    asm("{ .reg .u64 t; cvta.to.shared.u64 t, %1; cvt.u32.u64 %0, t; }" : "=r"(a) : "l"(p));
    return a;
}
__device__ __forceinline__ void cpa16(u32 dst, const void* src) {
    asm volatile("cp.async.cg.shared.global [%0], [%1], 16;" :: "r"(dst), "l"(src));
}
#define CPA_COMMIT() asm volatile("cp.async.commit_group;" ::: "memory")
#define CPA_WAIT1()  asm volatile("cp.async.wait_group 1;" ::: "memory")
#define CPA_WAIT0()  asm volatile("cp.async.wait_group 0;" ::: "memory")

__device__ __forceinline__ void mma8(float* d, const u32* a, const u32* b) {
    asm volatile("mma.sync.aligned.m16n8k8.row.col.f32.tf32.tf32.f32 "
        "{%0,%1,%2,%3}, {%4,%5,%6,%7}, {%8,%9}, {%0,%1,%2,%3};"
        : "+f"(d[0]), "+f"(d[1]), "+f"(d[2]), "+f"(d[3])
        : "r"(a[0]), "r"(a[1]), "r"(a[2]), "r"(a[3]), "r"(b[0]), "r"(b[1]));
}

// ---------------- SMEM layout (u32 offsets) ----------------
// sXp  [128][264]  X as (k,k+4) tf32 pairs (pad layout, CF)     135168 B
// sW1p [128 pr][32] u64  tf32 W1 image (pre-swizzled)            32768 B
// sW2p [16 pr][256] u64  tf32 W2 image (pre-swizzled)            32768 B
// sH   [128][36]   tf32 h tile (banks 4*gid+tig: CF)             18432 B
// sb1a [1024], sb2[256], toks[128]
#define XPS  264
#define HSd  36
#define OFF_X    0
#define OFF_W1   33792
#define OFF_W2   41984
#define OFF_H    50176
#define OFF_B1A  54784
#define OFF_B2   55808
#define OFF_TOKS 56064
#define SMEM_U32 56192
#define SMEM_BYTES (SMEM_U32 * 4)   // 224768

__global__ void __launch_bounds__(256, 1)
k_mlp(const float* __restrict__ X,  const float* __restrict__ B1v,
      const float* __restrict__ B2v, float* __restrict__ Y)
{
    extern __shared__ u32 smu[];
    u32*   sXp  = smu + OFF_X;
    u32*   sW1p = smu + OFF_W1;
    u32*   sW2p = smu + OFF_W2;
    u32*   sH   = smu + OFF_H;
    float* sb1a = (float*)(smu + OFF_B1A);
    float* sb2  = (float*)(smu + OFF_B2);
    int*   toks = (int*)(smu + OFF_TOKS);
    u32 sbase = smem_u32(smu);

    int tid  = threadIdx.x;
    int lane = tid & 31;
    int wid  = tid >> 5;
    int gid  = lane >> 2;
    int tig  = lane & 3;
    int m0  = (wid & 3) * 32;      // GEMM1: 4m x 2n
    int n0  = (wid >> 2) * 16;
    int m02 = (wid & 1) * 64;      // GEMM2: 2m x 4n
    int n02 = (wid >> 1) * 64;
    u32 swx = (u32)(tig << 2);     // pair-image bank XOR

    int bid = blockIdx.x;
    if (bid >= g_tile[NE]) return;
    int e = 0;
    while (bid >= g_tile[e + 1]) e++;
    int goff = g_off[e];
    int cnt  = g_off[e + 1] - goff;
    int t0   = (bid - g_tile[e]) * TM;
    int vcnt = min(TM, cnt - t0);

    const u32* w1img = gW1c + (size_t)e * NCHUNK * 8192;
    const u32* w2img = gW2c + (size_t)e * NCHUNK * 8192;
    const float* b1e = B1v + (size_t)e * HID;

    // ---- Prologue: cp.async chunk-0 images (straight 32 KB copies) ----
    #pragma unroll
    for (int i = 0; i < 8; i++) {
        int idx = i * 256 + tid;
        cpa16(sbase + (OFF_W1 + idx * 4) * 4, w1img + idx * 4);
    }
    CPA_COMMIT();
    #pragma unroll
    for (int i = 0; i < 8; i++) {
        int idx = i * 256 + tid;
        cpa16(sbase + (OFF_W2 + idx * 4) * 4, w2img + idx * 4);
    }
    CPA_COMMIT();

    if (tid < TM) {
        int slot = t0 + tid;
        if (slot >= cnt) slot = cnt - 1;
        toks[tid] = g_perm[goff + slot];
    }
    sb2[tid] = B2v[(size_t)e * OUTS + tid];
    *(float4*)&sb1a[tid * 4] = *(const float4*)(b1e + tid * 4);
    __syncthreads();

    // ---- Load X tile into (k,k+4) u64-pair layout ----
    #pragma unroll 4
    for (int it = 0; it < 16; it++) {
        int g = it * 256 + tid;
        int r = g >> 5;
        int c = g & 31;
        const float* xr = X + (size_t)toks[r] * INS + c * 8;
        float4 va = *(const float4*)xr;
        float4 vb = *(const float4*)(xr + 4);
        uint4 p01 = { f2tf32(va.x), f2tf32(vb.x), f2tf32(va.y), f2tf32(vb.y) };
        uint4 p23 = { f2tf32(va.z), f2tf32(vb.z), f2tf32(va.w), f2tf32(vb.w) };
        *(uint4*)&sXp[r * XPS + c * 8]     = p01;
        *(uint4*)&sXp[r * XPS + c * 8 + 4] = p23;
    }

    float yacc[4][8][4];
    #pragma unroll
    for (int mt = 0; mt < 4; mt++)
        #pragma unroll
        for (int nb = 0; nb < 8; nb++)
            #pragma unroll
            for (int j = 0; j < 4; j++) yacc[mt][nb][j] = 0.0f;

    const int rA0 = (m0 + gid) * XPS;
    const int rA1 = (m0 + 8 + gid) * XPS;
    const int rA2 = (m0 + 16 + gid) * XPS;
    const int rA3 = (m0 + 24 + gid) * XPS;
    const u32 cw0 = (u32)(n0 + gid) ^ swx;       // W1 image col, nb=0
    const u32 cw1 = (u32)(n0 + 8 + gid) ^ swx;   // W1 image col, nb=1

#define G1_LOADA(buf, kt) do {                                         \
    int pq = (kt) * 8 + tig * 2;                                       \
    uint2 A00 = *(const uint2*)&sXp[rA0 + pq];                         \
    uint2 A01 = *(const uint2*)&sXp[rA1 + pq];                         \
    uint2 A10 = *(const uint2*)&sXp[rA2 + pq];                         \
    uint2 A11 = *(const uint2*)&sXp[rA3 + pq];                         \
    aX[buf][0][0]=A00.x; aX[buf][0][2]=A00.y;                          \
    aX[buf][0][1]=A01.x; aX[buf][0][3]=A01.y;                          \
    aX[buf][1][0]=A10.x; aX[buf][1][2]=A10.y;                          \
    aX[buf][1][1]=A11.x; aX[buf][1][3]=A11.y;                          \
} while (0)

#define G1_LOADB(buf, kt) do {                                         \
    int pr = (kt) * 4 + tig;                                           \
    uint2 w0 = *(const uint2*)&sW1p[(pr * 32 + cw0) * 2];              \
    uint2 w1 = *(const uint2*)&sW1p[(pr * 32 + cw1) * 2];              \
    bW[buf][0] = w0.x; bW[buf][1] = w0.y;                              \
    bW[buf][2] = w1.x; bW[buf][3] = w1.y;                              \
} while (0)

#define G1_COMP(buf) do {                                              \
    mma8(acc1[0][0], aX[buf][0], &bW[buf][0]);                         \
    mma8(acc1[1][0], aX[buf][1], &bW[buf][0]);                         \
    mma8(acc1[0][1], aX[buf][0], &bW[buf][2]);                         \
    mma8(acc1[1][1], aX[buf][1], &bW[buf][2]);                         \
} while (0)

    for (int n = 0; n < NCHUNK; n++) {
        int h0 = n * HC;

        CPA_WAIT1();        // W1(n) landed
        __syncthreads();    // publish W1(n); sH(n-1)/sW1 reads done

        // ---- GEMM1: software-pipelined, fully unrolled ----
        float acc1[2][2][4];
        #pragma unroll
        for (int mt = 0; mt < 2; mt++)
            #pragma unroll
            for (int nb = 0; nb < 2; nb++)
                #pragma unroll
                for (int j = 0; j < 4; j++) acc1[mt][nb][j] = 0.0f;

        {
            u32 aX[2][2][4];
            u32 bW[2][4];
            G1_LOADA(0, 0); G1_LOADB(0, 0);
            #pragma unroll
            for (int kt = 0; kt < 32; kt++) {
                int cur = kt & 1, nxt = cur ^ 1;
                int ktn = (kt + 1) & 31;     // last prefetch redundant, harmless
                G1_LOADA(nxt, ktn);
                G1_LOADB(nxt, ktn);
                G1_COMP(cur);
            }
        }

        // ---- Epilogue A: relu(h + b1) -> tf32 -> sH ----
        #pragma unroll
        for (int mt = 0; mt < 2; mt++) {
            int r = m0 + 16 * mt + gid;
            #pragma unroll
            for (int nb = 0; nb < 2; nb++) {
                int c = n0 + 8 * nb + 2 * tig;
                float ba = sb1a[h0 + c], bb = sb1a[h0 + c + 1];
                uint2 lo = { f2tf32(fmaxf(acc1[mt][nb][0] + ba, 0.0f)),
                             f2tf32(fmaxf(acc1[mt][nb][1] + bb, 0.0f)) };
                uint2 hi = { f2tf32(fmaxf(acc1[mt][nb][2] + ba, 0.0f)),
                             f2tf32(fmaxf(acc1[mt][nb][3] + bb, 0.0f)) };
                *(uint2*)&sH[r * HSd + c]       = lo;
                *(uint2*)&sH[(r + 8) * HSd + c] = hi;
            }
        }

        CPA_WAIT0();        // W2(n) landed
        __syncthreads();    // publish sH(n) + W2(n); sW1 free

        // ---- Issue W1(n+1) (overlaps GEMM2) ----
        if (n + 1 < NCHUNK) {
            const u32* src = w1img + (size_t)(n + 1) * 8192;
            #pragma unroll
            for (int i = 0; i < 8; i++) {
                int idx = i * 256 + tid;
                cpa16(sbase + (OFF_W1 + idx * 4) * 4, src + idx * 4);
            }
        }
        CPA_COMMIT();

        // ---- GEMM2: Y[64r][64n]/warp += h @ W2chunk ----
        #pragma unroll
        for (int kt = 0; kt < 4; kt++) {
            int k0 = kt * 8;
            int pr = kt * 4 + tig;
            u32 ah[4][4];
            #pragma unroll
            for (int mt = 0; mt < 4; mt++) {
                int r = m02 + 16 * mt + gid;
                ah[mt][0] = sH[r * HSd + k0 + tig];
                ah[mt][1] = sH[(r + 8) * HSd + k0 + tig];
                ah[mt][2] = sH[r * HSd + k0 + tig + 4];
                ah[mt][3] = sH[(r + 8) * HSd + k0 + tig + 4];
            }
            #pragma unroll
            for (int nb = 0; nb < 8; nb++) {
                u32 ci = (u32)(n02 + 8 * nb + gid) ^ swx;
                uint2 w = *(const uint2*)&sW2p[(pr * 256 + ci) * 2];
                u32 b[2] = { w.x, w.y };
                mma8(yacc[0][nb], ah[0], b);
                mma8(yacc[1][nb], ah[1], b);
                mma8(yacc[2][nb], ah[2], b);
                mma8(yacc[3][nb], ah[3], b);
            }
        }
        __syncthreads();    // sW2 free

        // ---- Issue W2(n+1) (overlaps next GEMM1) ----
        if (n + 1 < NCHUNK) {
            const u32* src = w2img + (size_t)(n + 1) * 8192;
            #pragma unroll
            for (int i = 0; i < 8; i++) {
                int idx = i * 256 + tid;
                cpa16(sbase + (OFF_W2 + idx * 4) * 4, src + idx * 4);
            }
        }
        CPA_COMMIT();
    }

    // ---- Final: Y + b2, masked scatter store ----
    #pragma unroll
    for (int mt = 0; mt < 4; mt++) {
        int  rA = m02 + 16 * mt + gid, rB = rA + 8;
        bool vA = rA < vcnt, vB = rB < vcnt;
        float* yA = Y + (size_t)toks[rA] * OUTS;
        float* yB = Y + (size_t)toks[rB] * OUTS;
        #pragma unroll
        for (int nb = 0; nb < 8; nb++) {
            int c = n02 + 8 * nb + 2 * tig;
            float ba = sb2[c], bb = sb2[c + 1];
            if (vA) { float2 v = { yacc[mt][nb][0] + ba, yacc[mt][nb][1] + bb }; *(float2*)(yA + c) = v; }
            if (vB) { float2 v = { yacc[mt][nb][2] + ba, yacc[mt][nb][3] + bb }; *(float2*)(yB + c) = v; }
        }
    }
}

// ---------------- launch ----------------
extern "C" void kernel_launch(void* const* d_in, const int* in_sizes, int n_in,
                              void* d_out, int out_size)
{
    (void)out_size;
    const float *X = 0, *W1 = 0, *B1 = 0, *W2 = 0, *B2 = 0;
    const void  *IDS = 0;
    for (int i = 0; i < n_in; i++) {
        switch (in_sizes[i]) {
            case 33554432: X = (const float*)d_in[i]; break;
            case 4194304:  if (!W1) W1 = (const float*)d_in[i];
                           else     W2 = (const float*)d_in[i];
                           break;
            case 16384:    B1 = (const float*)d_in[i]; break;
            case 4096:     B2 = (const float*)d_in[i]; break;
            case 131072:   IDS = d_in[i]; break;
            default: break;
        }
    }
    float* Y = (float*)d_out;

    cudaFuncSetAttribute(k_mlp, cudaFuncAttributeMaxDynamicSharedMemorySize, SMEM_BYTES);

    k_pre<<<512, 256>>>(W1, W2, (const long long*)IDS);
    k_count_scan<<<256, 256>>>(IDS);
    k_scatter<<<256, 256>>>(IDS);
    k_mlp<<<GRID2, 256, SMEM_BYTES>>>(X, B1, B2, Y);
}